// round 16
// baseline (speedup 1.0000x reference)
#include <cuda_runtime.h>
#include <cstdint>

// Problem constants (fixed by the dataset).
#define E_EDGES 8192u
#define N_NODES 4096u
#define TOTAL (1u << 26)         // E*E elements
#define KOUT 16384               // K*E output rows
#define NBUCK 4096u              // kept-index buckets (t >> 14)
#define BSLOTS 64u               // slots per bucket (avg load ~4)
#define T9C (8192u << 9)         // conservative candidate threshold (p = 1/1024)
#define CAND_CAP 262144u         // candidate buffer (expected ~65k, 4x margin)

// ---------------- device scratch (static allocations only) ----------------
__device__ unsigned g_cnt_d[N_NODES];
__device__ unsigned g_deg[N_NODES];
__device__ unsigned g_off[N_NODES + 1];
__device__ unsigned g_cursor[N_NODES];
__device__ int g_adj[E_EDGES];
__device__ unsigned long long g_numneg;
__device__ unsigned g_T9;                      // exact threshold << 9
__device__ unsigned g_cand_cnt;
__device__ uint2 g_cand[CAND_CAP];             // (t, bits) candidates
__device__ unsigned g_bcnt[NBUCK];
__device__ unsigned g_boff[NBUCK];
__device__ unsigned g_bslot[NBUCK * BSLOTS];

// ------- threefry-2x32, key = (0, 42), partitionable layout (validated) -------
#define TF_ROUND_M(r) { x0 += x1;                                            \
    unsigned long long w = (unsigned long long)x1 * (1ull << (r));           \
    x1 = ((unsigned)w | (unsigned)(w >> 32)) ^ x0; }

__device__ __forceinline__ unsigned tf_bits(unsigned t) {
    const unsigned ks0 = 0u, ks1 = 42u, ks2 = 0x1BD11BDAu ^ 42u;
    unsigned x0 = 0u;            // counts_hi + ks0
    unsigned x1 = t + ks1;       // counts_lo + ks1
    TF_ROUND_M(13) TF_ROUND_M(15) TF_ROUND_M(26) TF_ROUND_M(6)
    x0 += ks1; x1 += ks2 + 1u;
    TF_ROUND_M(17) TF_ROUND_M(29) TF_ROUND_M(16) TF_ROUND_M(24)
    x0 += ks2; x1 += ks0 + 2u;
    TF_ROUND_M(13) TF_ROUND_M(15) TF_ROUND_M(26) TF_ROUND_M(6)
    x0 += ks0; x1 += ks1 + 3u;
    TF_ROUND_M(17) TF_ROUND_M(29) TF_ROUND_M(16) TF_ROUND_M(24)
    x0 += ks1; x1 += ks2 + 4u;
    TF_ROUND_M(13) TF_ROUND_M(15) TF_ROUND_M(26) TF_ROUND_M(6)
    x0 += ks2; x1 += ks0 + 5u;
    return x0 ^ x1;
}

// ---------------- init: zero all counters ----------------
__global__ void k_init() {
    unsigned tid = blockIdx.x * blockDim.x + threadIdx.x;   // 4096 threads
    g_bcnt[tid] = 0u;
    g_cnt_d[tid] = 0u; g_deg[tid] = 0u; g_cursor[tid] = 0u;
    if (tid == 0) { g_numneg = 0ull; g_cand_cnt = 0u; }
}

// ---------------- setup chain (runs concurrently with k_phase1) -------------
__global__ void k_hist(const int* __restrict__ src, const int* __restrict__ dst) {
    unsigned e = blockIdx.x * blockDim.x + threadIdx.x;
    if (e < E_EDGES) {
        unsigned d = (unsigned)dst[e], s = (unsigned)src[e];
        if (d < N_NODES) atomicAdd(&g_cnt_d[d], 1u);
        if (s < N_NODES) atomicAdd(&g_deg[s], 1u);
    }
}

__global__ void k_scan_deg() {  // 1 block, 1024 threads, 4 elems/thread
    __shared__ unsigned s[1024];
    unsigned t = threadIdx.x;
    unsigned v[4], sum = 0;
#pragma unroll
    for (int k = 0; k < 4; k++) { v[k] = g_deg[t * 4 + k]; sum += v[k]; }
    s[t] = sum; __syncthreads();
    for (int d = 1; d < 1024; d <<= 1) {
        unsigned a = (t >= (unsigned)d) ? s[t - d] : 0u;
        __syncthreads();
        s[t] += a;
        __syncthreads();
    }
    unsigned excl = (t == 0) ? 0u : s[t - 1];
#pragma unroll
    for (int k = 0; k < 4; k++) { g_off[t * 4 + k] = excl; excl += v[k]; }
    if (t == 1023) g_off[N_NODES] = excl;
}

__global__ void k_fill(const int* __restrict__ src, const int* __restrict__ dst) {
    unsigned e = blockIdx.x * blockDim.x + threadIdx.x;
    if (e < E_EDGES) {
        unsigned s = (unsigned)src[e];
        if (s < N_NODES) {
            unsigned pos = atomicAdd(&g_cursor[s], 1u);
            unsigned slot = g_off[s] + pos;
            if (slot < E_EDGES) g_adj[slot] = dst[e];
        }
    }
}

__global__ void k_rowcount() {
    unsigned s = blockIdx.x * blockDim.x + threadIdx.x;
    if (s >= N_NODES) return;
    unsigned o = g_off[s], e = g_off[s + 1];
    unsigned d = e - o;
    if (d == 0) return;
    unsigned X = g_cnt_d[s];
    for (unsigned a = o; a < e; a++) {
        int v = g_adj[a];
        if (v == (int)s) continue;
        bool dup = false;
        for (unsigned b = o; b < a; b++) if (g_adj[b] == v) { dup = true; break; }
        if (!dup && (unsigned)v < N_NODES) X += g_cnt_d[v];
    }
    atomicAdd(&g_numneg, (unsigned long long)d * (unsigned long long)(E_EDGES - X));
}

__global__ void k_thresh() {
    unsigned long long nn = g_numneg;
    unsigned long long ratio = nn >> 13;  // // E
    unsigned T;
    if (ratio == 0ull) {
        T = 1u << 23;
    } else {
        float p = __fdiv_rn(2.0f, (float)ratio);   // matches jnp float32 divide
        double pt = (double)p * 8388608.0;          // p * 2^23 (exact)
        double ct = ceil(pt);
        T = (ct >= 8388608.0) ? (1u << 23) : (unsigned)ct;
    }
    g_T9 = (T >= (1u << 23)) ? 0xFFFFFFFFu : (T << 9);
}

// ------- phase 1: pure threefry scan, store conservative candidates ---------
#define PER 8
__global__ void __launch_bounds__(256) k_phase1() {
    unsigned base = (blockIdx.x * 256u + threadIdx.x) * PER;
#pragma unroll
    for (int u = 0; u < PER; u++) {
        unsigned c = base + u;
        unsigned bits = tf_bits(c);
        if (bits < T9C) {
            unsigned pos = atomicAdd(&g_cand_cnt, 1u);
            if (pos < CAND_CAP) g_cand[pos] = make_uint2(c, bits);
        }
    }
}

// ---------------- shared keep logic (mask check + bucket scatter) -----------
__device__ __forceinline__ void try_keep(unsigned t,
                                         const int* __restrict__ src,
                                         const int* __restrict__ dst) {
    unsigned i = t >> 13, j = t & (E_EDGES - 1u);
    int s = src[i];
    int dj = dst[j];
    if (dj == s) return;
    unsigned o = g_off[s], e = g_off[s + 1];
    for (unsigned k = o; k < e; k++)
        if (g_adj[k] == dj) return;
    unsigned b = t >> 14;
    unsigned pos = atomicAdd(&g_bcnt[b], 1u);
    if (pos < BSLOTS) g_bslot[b * BSLOTS + pos] = t;
}

// ------- phase 2: exact-threshold filter over candidates -------
__global__ void __launch_bounds__(256) k_filter(const int* __restrict__ src,
                                                const int* __restrict__ dst) {
    if (g_T9 > T9C || g_cand_cnt > CAND_CAP) return;   // fallback path owns it
    unsigned q = blockIdx.x * 256u + threadIdx.x;
    if (q >= g_cand_cnt) return;
    uint2 cb = g_cand[q];
    if (cb.y < g_T9) try_keep(cb.x, src, dst);
}

// ------- fallback: full rescan (inert for this dataset; correctness guard) --
__global__ void __launch_bounds__(256) k_fallback(const int* __restrict__ src,
                                                  const int* __restrict__ dst) {
    unsigned T9 = g_T9;
    if (T9 <= T9C && g_cand_cnt <= CAND_CAP) return;   // normal path: no-op
    unsigned base = (blockIdx.x * 256u + threadIdx.x) * 128u;  // 2048 blocks
#pragma unroll 8
    for (unsigned u = 0; u < 128u; u++) {
        unsigned c = base + u;
        if (tf_bits(c) < T9) try_keep(c, src, dst);
    }
}

// ------- scan bucket counts (1 block) + fused output pad init -------
__global__ void __launch_bounds__(1024) k_scan_buckets(
        const int* __restrict__ src, const int* __restrict__ dst,
        float* __restrict__ out, int out_size) {
    __shared__ unsigned s[1024];
    unsigned t = threadIdx.x;
    unsigned v[4], sum = 0;
#pragma unroll
    for (int k = 0; k < 4; k++) { v[k] = g_bcnt[t * 4 + k]; sum += v[k]; }
    s[t] = sum; __syncthreads();
    for (int d = 1; d < 1024; d <<= 1) {
        unsigned a = (t >= (unsigned)d) ? s[t - d] : 0u;
        __syncthreads();
        s[t] += a;
        __syncthreads();
    }
    unsigned excl = (t == 0) ? 0u : s[t - 1];
#pragma unroll
    for (int k = 0; k < 4; k++) { g_boff[t * 4 + k] = excl; excl += v[k]; }

    float pad_s = (float)src[0], pad_d = (float)dst[0];
    for (unsigned q = t; q < KOUT; q += 1024) {
        if ((int)q < out_size) out[q] = pad_s;
        if ((int)(KOUT + q) < out_size) out[KOUT + q] = pad_d;
    }
}

// ------- sort-emit: one warp per bucket, rank ≤64 distinct entries -------
__global__ void __launch_bounds__(256) k_sort_emit(
        const int* __restrict__ src, const int* __restrict__ dst,
        float* __restrict__ out, int out_size) {
    __shared__ unsigned svals[8][BSLOTS];
    unsigned warp = threadIdx.x >> 5, lane = threadIdx.x & 31u;
    unsigned b = blockIdx.x * 8u + warp;          // 512 blocks x 8 warps = 4096
    unsigned n = g_bcnt[b];
    if (n > BSLOTS) n = BSLOTS;
    if (n == 0) return;
    unsigned off = g_boff[b];
    if (off >= KOUT) return;
    for (unsigned l = lane; l < n; l += 32) svals[warp][l] = g_bslot[b * BSLOTS + l];
    __syncwarp();
    for (unsigned l = lane; l < n; l += 32) {
        unsigned mine = svals[warp][l];
        unsigned rank = 0;
        for (unsigned j = 0; j < n; j++) rank += (svals[warp][j] < mine) ? 1u : 0u;
        unsigned pos = off + rank;
        if (pos < KOUT) {
            if ((int)pos < out_size) out[pos] = (float)src[mine >> 13];
            if ((int)(KOUT + pos) < out_size)
                out[KOUT + pos] = (float)dst[mine & (E_EDGES - 1u)];
        }
    }
}

// ---------------- launch: fork/join two-stream capture topology -------------
extern "C" void kernel_launch(void* const* d_in, const int* in_sizes, int n_in,
                              void* d_out, int out_size) {
    const int* src;
    const int* dst;
    if (n_in >= 3 && in_sizes[0] == (int)E_EDGES) {
        dst = (const int*)d_in[0];   // alphabetical: edge_dst first
        src = (const int*)d_in[1];
    } else {
        src = (const int*)d_in[1];   // dict order: node_feature first
        dst = (const int*)d_in[2];
    }
    float* out = (float*)d_out;

    // Static side stream + events: created on the first (uncaptured)
    // correctness call, reused (and captured as graph edges) afterwards.
    static cudaStream_t s_side = nullptr;
    static cudaEvent_t e_fork = nullptr, e_join = nullptr;
    if (s_side == nullptr) {
        cudaStreamCreateWithFlags(&s_side, cudaStreamNonBlocking);
        cudaEventCreateWithFlags(&e_fork, cudaEventDisableTiming);
        cudaEventCreateWithFlags(&e_join, cudaEventDisableTiming);
    }

    k_init<<<NBUCK / 256, 256>>>();

    // fork: big threefry scan on the side stream
    cudaEventRecord(e_fork, 0);
    cudaStreamWaitEvent(s_side, e_fork, 0);
    k_phase1<<<TOTAL / (256 * PER), 256, 0, s_side>>>();
    cudaEventRecord(e_join, s_side);

    // setup chain on the main (capture) stream, concurrent with k_phase1
    k_hist<<<E_EDGES / 256, 256>>>(src, dst);
    k_scan_deg<<<1, 1024>>>();
    k_fill<<<E_EDGES / 256, 256>>>(src, dst);
    k_rowcount<<<N_NODES / 256, 256>>>();
    k_thresh<<<1, 1>>>();

    // join, then exact filter + (inert) fallback + compaction
    cudaStreamWaitEvent(0, e_join, 0);
    k_filter<<<CAND_CAP / 256, 256>>>(src, dst);
    k_fallback<<<TOTAL / (256 * 128), 256>>>(src, dst);
    k_scan_buckets<<<1, 1024>>>(src, dst, out, out_size);
    k_sort_emit<<<NBUCK / 8, 256>>>(src, dst, out, out_size);
}